// round 3
// baseline (speedup 1.0000x reference)
#include <cuda_runtime.h>
#include <math.h>

#define P 262144          // 512*512
#define NCH 16
#define NIMG 8
#define KSEG 33
#define STR 17            // row stride for [id][e] accumulators; 17 invertible mod 32 -> conflict-free scatter
#define DELTA_V 0.5f
#define DELTA_D 1.5f
#define GAMMA_W 0.001f
#define FULL 0xffffffffu

// Scratch (device globals: no allocation allowed)
__device__ float g_acc[NIMG][KSEG * STR];  // per image: [id*17 + e], slot 16 = count
__device__ float g_var[NIMG][KSEG];

__global__ void k_zero() {
    int t = threadIdx.x;
    float* a = &g_acc[0][0];
    for (int i = t; i < NIMG * KSEG * STR; i += blockDim.x) a[i] = 0.f;
    float* v = &g_var[0][0];
    for (int i = t; i < NIMG * KSEG; i += blockDim.x) v[i] = 0.f;
}

// Pass 1: per-segment sums + counts.
// grid (64, 8), 256 threads. Each block: 4096 pixels of one image.
__global__ __launch_bounds__(256) void k_accum(const float* __restrict__ emb,
                                               const int* __restrict__ mask) {
    __shared__ float wacc[8][KSEG * STR];   // per-warp private accumulators
    const int tid = threadIdx.x, w = tid >> 5, lane = tid & 31;
    const int img = blockIdx.y;

    for (int i = tid; i < 8 * KSEG * STR; i += 256) (&wacc[0][0])[i] = 0.f;
    __syncthreads();

    const float* eb = emb + (size_t)img * NCH * P;
    const int*   mb = mask + (size_t)img * P;
    const int base = blockIdx.x * 4096 + w * 512 + lane;
    volatile float* acc = wacc[w];

    for (int it = 0; it < 16; ++it) {
        const int p = base + it * 32;
        const int id = mb[p];
        float v[NCH];
#pragma unroll
        for (int e = 0; e < NCH; e++) v[e] = eb[e * P + p];

        // serialize same-id lanes; distinct-id lanes scatter race-free
        const unsigned peers = __match_any_sync(FULL, id);
        const int rank = __popc(peers & ((1u << lane) - 1u));
        for (int r = 0;; r++) {
            if (!__ballot_sync(FULL, rank == r)) break;
            if (rank == r) {
                volatile float* a = acc + id * STR;
#pragma unroll
                for (int e = 0; e < NCH; e++) a[e] += v[e];
                a[NCH] += 1.0f;
            }
        }
    }
    __syncthreads();

    for (int i = tid; i < KSEG * STR; i += 256) {
        float s = 0.f;
#pragma unroll
        for (int w2 = 0; w2 < 8; w2++) s += wacc[w2][i];
        atomicAdd(&g_acc[img][i], s);
    }
}

// Pass 2: variance hinge term per segment. Means held in registers, one instance per lane.
__global__ __launch_bounds__(256) void k_var(const float* __restrict__ emb,
                                             const int* __restrict__ mask) {
    __shared__ float wvar[8][KSEG + 1];     // stride 34
    const int tid = threadIdx.x, w = tid >> 5, lane = tid & 31;
    const int img = blockIdx.y;

    for (int i = tid; i < 8 * (KSEG + 1); i += 256) (&wvar[0][0])[i] = 0.f;
    __syncthreads();

    // lane l holds mean row for instance id = l+1 (segment 0 never matters for var)
    float murow[NCH];
    {
        const float* ga = g_acc[img] + (lane + 1) * STR;
        const float cc = fmaxf(ga[NCH], 1.f);
#pragma unroll
        for (int e = 0; e < NCH; e++) murow[e] = ga[e] / cc;
    }

    const float* eb = emb + (size_t)img * NCH * P;
    const int*   mb = mask + (size_t)img * P;
    const int base = blockIdx.x * 4096 + w * 512 + lane;
    volatile float* vacc = wvar[w];

    for (int it = 0; it < 16; ++it) {
        const int p = base + it * 32;
        const int id = mb[p];
        int idx = id - 1; if (idx < 0) idx = 0;

        float v[NCH];
#pragma unroll
        for (int e = 0; e < NCH; e++) v[e] = eb[e * P + p];

        float sq = 0.f;
#pragma unroll
        for (int e = 0; e < NCH; e++) {
            const float me = __shfl_sync(FULL, murow[e], idx);
            const float d = v[e] - me;
            sq = fmaf(d, d, sq);
        }
        const float pd = (sq > 0.f) ? sqrtf(sq) : 0.f;
        float t = fmaxf(pd - DELTA_V, 0.f);
        t = t * t;
        const bool go = (id != 0) && (t > 0.f);

        // unique keys for non-participants -> contiguous ranks within each active id group
        const int key = go ? id : (1000 + lane);
        const unsigned peers = __match_any_sync(FULL, key);
        const int rank = __popc(peers & ((1u << lane) - 1u));
        for (int r = 0;; r++) {
            if (!__ballot_sync(FULL, (rank == r) && go)) break;
            if ((rank == r) && go) vacc[id] += t;
        }
    }
    __syncthreads();

    for (int i = tid; i < KSEG; i += 256) {
        float s = 0.f;
#pragma unroll
        for (int w2 = 0; w2 < 8; w2++) s += wvar[w2][i];
        atomicAdd(&g_var[img][i], s);
    }
}

__device__ __forceinline__ float wsum(float x) {
#pragma unroll
    for (int o = 16; o > 0; o >>= 1) x += __shfl_xor_sync(FULL, x, o);
    return x;
}

// Finalize: means -> dist/reg/var losses, combine across images. One block, warp = image.
__global__ __launch_bounds__(256) void k_final(float* __restrict__ out) {
    __shared__ float sv[NIMG], sd[NIMG], sr[NIMG], sva[NIMG];
    const int tid = threadIdx.x, w = tid >> 5, lane = tid & 31;

    const float* ga = g_acc[w];
    const int id = lane + 1;                       // instance 1..32
    const float cnt = ga[id * STR + NCH];
    const bool pres = cnt > 0.f;
    const float cc = fmaxf(cnt, 1.f);
    float mu[NCH];
#pragma unroll
    for (int e = 0; e < NCH; e++) mu[e] = ga[id * STR + e] / cc;

    const unsigned pb = __ballot_sync(FULL, pres);
    const float n_inst = (float)__popc(pb);

    float var_l = pres ? (g_var[w][id] / cc) : 0.f;

    float sqm = 0.f;
#pragma unroll
    for (int e = 0; e < NCH; e++) sqm = fmaf(mu[e], mu[e], sqm);
    const float nrm = (sqm > 0.f) ? sqrtf(sqm) : 0.f;
    float reg_l = pres ? nrm : 0.f;

    float dsum = 0.f, pcount = 0.f;
    for (int b = 1; b < 32; b++) {
        float dsq = 0.f;
#pragma unroll
        for (int e = 0; e < NCH; e++) {
            const float me = __shfl_sync(FULL, mu[e], b);
            const float d = mu[e] - me;
            dsq = fmaf(d, d, dsq);
        }
        const bool pb2 = (pb >> b) & 1u;
        if ((lane < b) && pres && pb2) {
            const float dd = (dsq > 0.f) ? sqrtf(dsq) : 0.f;
            const float tt = fmaxf(2.f * DELTA_D - dd, 0.f);
            dsum = fmaf(tt, tt, dsum);
            pcount += 1.f;
        }
    }

    const float var_s = wsum(var_l);
    const float reg_s = wsum(reg_l);
    const float dst_s = wsum(dsum);
    const float pcs   = wsum(pcount);

    if (lane == 0) {
        const float valid = (n_inst > 0.f) ? 1.f : 0.f;
        const float denom = fmaxf(n_inst, 1.f);
        float vloss = var_s / denom;
        float rloss = reg_s / denom;
        float dloss = (dst_s / fmaxf(pcs, 1.f)) * ((n_inst > 1.f) ? 1.f : 0.f);
        sv[w] = vloss * valid;
        sd[w] = dloss * valid;
        sr[w] = rloss * valid;
        sva[w] = valid;
    }
    __syncthreads();
    if (tid == 0) {
        float vs = 0.f, v = 0.f, d = 0.f, r = 0.f;
        for (int i = 0; i < NIMG; i++) { vs += sva[i]; v += sv[i]; d += sd[i]; r += sr[i]; }
        vs = fmaxf(vs, 1.f);
        v /= vs; d /= vs; r /= vs;
        out[0] = v + d + GAMMA_W * r;
        out[1] = v;
        out[2] = d;
        out[3] = r;
    }
}

extern "C" void kernel_launch(void* const* d_in, const int* in_sizes, int n_in,
                              void* d_out, int out_size) {
    const float* emb = (const float*)d_in[0];
    const int* mask = (const int*)d_in[1];
    float* out = (float*)d_out;

    k_zero<<<1, 256>>>();
    k_accum<<<dim3(64, NIMG), 256>>>(emb, mask);
    k_var<<<dim3(64, NIMG), 256>>>(emb, mask);
    k_final<<<1, 256>>>(out);
}

// round 5
// speedup vs baseline: 1.3388x; 1.3388x over previous
#include <cuda_runtime.h>
#include <math.h>

#define P 262144          // 512*512
#define NCH 16
#define NIMG 8
#define KSEG 33
#define STR 17            // row stride: 17 invertible mod 32 -> conflict-free scatter
#define DELTA_V 0.5f
#define DELTA_D 1.5f
#define GAMMA_W 0.001f
#define FULL 0xffffffffu

// Scratch (device globals: zero-initialized at module load; k_final re-zeroes
// them after use so every graph replay sees zeros).
__device__ float g_acc[NIMG][KSEG * STR];  // [id*17 + e], slot 16 = count
__device__ float g_var[NIMG][KSEG];

// Pass 1: per-segment sums + counts. grid (64, 8) x 256 thr; block = 4096 px.
__global__ __launch_bounds__(256) void k_accum(const float* __restrict__ emb,
                                               const int* __restrict__ mask) {
    __shared__ float wacc[8][KSEG * STR];   // per-warp private accumulators
    const int tid = threadIdx.x, w = tid >> 5, lane = tid & 31;
    const int img = blockIdx.y;

    for (int i = tid; i < 8 * KSEG * STR; i += 256) (&wacc[0][0])[i] = 0.f;
    __syncthreads();

    const float* eb = emb + (size_t)img * NCH * P;
    const int*   mb = mask + (size_t)img * P;
    const int wbase = blockIdx.x * 4096 + w * 512;
    float* acc = wacc[w];                   // NOT volatile: alias analysis keeps
                                            // order; ballot reconverges rounds.
    for (int it = 0; it < 8; ++it) {
        const int p0 = wbase + it * 64 + lane * 2;
        const int2 mid = *reinterpret_cast<const int2*>(mb + p0);
        float v[2][NCH];
#pragma unroll
        for (int e = 0; e < NCH; e++) {
            const float2 t = *reinterpret_cast<const float2*>(eb + (size_t)e * P + p0);
            v[0][e] = t.x; v[1][e] = t.y;
        }
        const int ids[2] = {mid.x, mid.y};
#pragma unroll
        for (int s = 0; s < 2; s++) {
            const int id = ids[s];
            const unsigned peers = __match_any_sync(FULL, id);
            const int rank = __popc(peers & ((1u << lane) - 1u));
            float* a = acc + id * STR;
            for (int r = 0;; r++) {
                if (!__ballot_sync(FULL, rank == r)) break;
                if (rank == r) {
#pragma unroll
                    for (int e = 0; e < NCH; e++) a[e] += v[s][e];
                    a[NCH] += 1.0f;
                }
            }
        }
    }
    __syncthreads();

    for (int i = tid; i < KSEG * STR; i += 256) {
        float s = 0.f;
#pragma unroll
        for (int w2 = 0; w2 < 8; w2++) s += wacc[w2][i];
        atomicAdd(&g_acc[img][i], s);
    }
}

// Pass 2: variance hinge. Means in registers (lane l <-> id l+1), shfl gather.
// Block/image mapping REVERSED vs pass 1 so the first wave re-reads what pass 1
// left resident in L2 (tail of the 136MB stream).
__global__ __launch_bounds__(256) void k_var(const float* __restrict__ emb,
                                             const int* __restrict__ mask) {
    __shared__ float wvar[8][KSEG + 1];     // stride 34
    const int tid = threadIdx.x, w = tid >> 5, lane = tid & 31;
    const int img = (NIMG - 1) - blockIdx.y;
    const int bx  = 63 - blockIdx.x;

    for (int i = tid; i < 8 * (KSEG + 1); i += 256) (&wvar[0][0])[i] = 0.f;
    __syncthreads();

    float murow[NCH];
    {
        const float* ga = g_acc[img] + (lane + 1) * STR;
        const float cc = fmaxf(ga[NCH], 1.f);
#pragma unroll
        for (int e = 0; e < NCH; e++) murow[e] = ga[e] / cc;
    }

    const float* eb = emb + (size_t)img * NCH * P;
    const int*   mb = mask + (size_t)img * P;
    const int wbase = bx * 4096 + w * 512;
    float* vacc = wvar[w];

    for (int it = 0; it < 8; ++it) {
        const int p0 = wbase + it * 64 + lane * 2;
        const int2 mid = *reinterpret_cast<const int2*>(mb + p0);
        float v[2][NCH];
#pragma unroll
        for (int e = 0; e < NCH; e++) {
            const float2 t = *reinterpret_cast<const float2*>(eb + (size_t)e * P + p0);
            v[0][e] = t.x; v[1][e] = t.y;
        }
        const int ids[2] = {mid.x, mid.y};
#pragma unroll
        for (int s = 0; s < 2; s++) {
            const int id = ids[s];
            int idx = id - 1; if (idx < 0) idx = 0;
            float sq = 0.f;
#pragma unroll
            for (int e = 0; e < NCH; e++) {
                const float me = __shfl_sync(FULL, murow[e], idx);
                const float d = v[s][e] - me;
                sq = fmaf(d, d, sq);
            }
            const float pd = (sq > 0.f) ? sqrtf(sq) : 0.f;
            float t = fmaxf(pd - DELTA_V, 0.f);
            t = t * t;
            const bool go = (id != 0) && (t > 0.f);
            const int key = go ? id : (1000 + lane);
            const unsigned peers = __match_any_sync(FULL, key);
            const int rank = __popc(peers & ((1u << lane) - 1u));
            for (int r = 0;; r++) {
                if (!__ballot_sync(FULL, (rank == r) && go)) break;
                if ((rank == r) && go) vacc[id] += t;
            }
        }
    }
    __syncthreads();

    for (int i = tid; i < KSEG; i += 256) {
        float s = 0.f;
#pragma unroll
        for (int w2 = 0; w2 < 8; w2++) s += wvar[w2][i];
        atomicAdd(&g_var[img][i], s);
    }
}

__device__ __forceinline__ float wsum(float x) {
#pragma unroll
    for (int o = 16; o > 0; o >>= 1) x += __shfl_xor_sync(FULL, x, o);
    return x;
}

// Finalize: pairwise via smem (broadcast reads, no shfl chain), then re-zero scratch.
__global__ __launch_bounds__(256) void k_final(float* __restrict__ out) {
    __shared__ float smu[NIMG][32][NCH + 1];   // pad 17: conflict-free stores
    __shared__ float sv[NIMG], sd[NIMG], sr[NIMG], sva[NIMG];
    const int tid = threadIdx.x, w = tid >> 5, lane = tid & 31;

    const float* ga = g_acc[w];
    const int id = lane + 1;                   // instance 1..32
    const float cnt = ga[id * STR + NCH];
    const bool pres = cnt > 0.f;
    const float cc = fmaxf(cnt, 1.f);
    float mu[NCH];
#pragma unroll
    for (int e = 0; e < NCH; e++) {
        mu[e] = ga[id * STR + e] / cc;
        smu[w][lane][e] = mu[e];
    }
    __syncwarp();

    const unsigned pb = __ballot_sync(FULL, pres);
    const float n_inst = (float)__popc(pb);

    const float var_l = pres ? (g_var[w][id] / cc) : 0.f;

    float sqm = 0.f;
#pragma unroll
    for (int e = 0; e < NCH; e++) sqm = fmaf(mu[e], mu[e], sqm);
    const float reg_l = pres ? ((sqm > 0.f) ? sqrtf(sqm) : 0.f) : 0.f;

    float dsum = 0.f, pcount = 0.f;
#pragma unroll 4
    for (int b = 1; b < 32; b++) {
        float dsq = 0.f;
#pragma unroll
        for (int e = 0; e < NCH; e++) {
            const float d = mu[e] - smu[w][b][e];   // broadcast read
            dsq = fmaf(d, d, dsq);
        }
        if ((lane < b) && pres && ((pb >> b) & 1u)) {
            const float dd = (dsq > 0.f) ? sqrtf(dsq) : 0.f;
            const float tt = fmaxf(2.f * DELTA_D - dd, 0.f);
            dsum = fmaf(tt, tt, dsum);
            pcount += 1.f;
        }
    }

    const float var_s = wsum(var_l);
    const float reg_s = wsum(reg_l);
    const float dst_s = wsum(dsum);
    const float pcs   = wsum(pcount);

    if (lane == 0) {
        const float valid = (n_inst > 0.f) ? 1.f : 0.f;
        const float denom = fmaxf(n_inst, 1.f);
        sv[w]  = (var_s / denom) * valid;
        sr[w]  = (reg_s / denom) * valid;
        sd[w]  = (dst_s / fmaxf(pcs, 1.f)) * ((n_inst > 1.f) ? 1.f : 0.f) * valid;
        sva[w] = valid;
    }
    __syncthreads();

    if (tid == 0) {
        float vs = 0.f, v = 0.f, d = 0.f, r = 0.f;
        for (int i = 0; i < NIMG; i++) { vs += sva[i]; v += sv[i]; d += sd[i]; r += sr[i]; }
        vs = fmaxf(vs, 1.f);
        v /= vs; d /= vs; r /= vs;
        out[0] = v + d + GAMMA_W * r;
        out[1] = v;
        out[2] = d;
        out[3] = r;
    }

    // Re-zero scratch for the next replay (all reads of g_acc/g_var happened
    // before the __syncthreads above).
    float* a = &g_acc[0][0];
    for (int i = tid; i < NIMG * KSEG * STR; i += 256) a[i] = 0.f;
    float* vvp = &g_var[0][0];
    for (int i = tid; i < NIMG * KSEG; i += 256) vvp[i] = 0.f;
}

extern "C" void kernel_launch(void* const* d_in, const int* in_sizes, int n_in,
                              void* d_out, int out_size) {
    const float* emb = (const float*)d_in[0];
    const int* mask = (const int*)d_in[1];
    float* out = (float*)d_out;

    k_accum<<<dim3(64, NIMG), 256>>>(emb, mask);
    k_var<<<dim3(64, NIMG), 256>>>(emb, mask);
    k_final<<<1, 256>>>(out);
}

// round 7
// speedup vs baseline: 1.7745x; 1.3254x over previous
#include <cuda_runtime.h>
#include <math.h>

#define P 262144          // 512*512
#define NCH 16
#define NIMG 8
#define KSEG 33
#define NID 32            // ids 1..32 stored at row id-1; id 0 excluded everywhere
#define STR 17            // row stride: 17 invertible mod 32 -> conflict-free scatter
#define ACCN (NID * STR)  // 544 floats per accumulator copy
#define DELTA_V 0.5f
#define DELTA_D 1.5f
#define GAMMA_W 0.001f
#define FULL 0xffffffffu

// Scratch (zero-initialized at load; k_final re-zeroes after use per replay).
__device__ float g_acc[NIMG][ACCN];   // [(id-1)*17 + e], slot 16 = count
__device__ float g_vsum[NIMG];        // per-image sum of t * invc

// Pass 1: per-segment sums + counts. grid (128, 8) x 256 thr; block = 2048 px.
// Per-warp accumulators with R=2 rank-replicas: lanes with equal rank have
// distinct ids, so ranks {2r, 2r+1} scatter concurrently (replica = rank&1).
__global__ __launch_bounds__(256) void k_accum(const float* __restrict__ emb,
                                               const int* __restrict__ mask) {
    __shared__ float wacc[8][2][ACCN];   // 34.8 KB
    const int tid = threadIdx.x, w = tid >> 5, lane = tid & 31;
    const int img = blockIdx.y;

    for (int i = tid; i < 8 * 2 * ACCN; i += 256) (&wacc[0][0][0])[i] = 0.f;
    __syncthreads();

    const float* eb = emb + (size_t)img * NCH * P;
    const int*   mb = mask + (size_t)img * P;
    const int wbase = blockIdx.x * 2048 + w * 256;
    const unsigned below = (1u << lane) - 1u;

    for (int it = 0; it < 4; ++it) {
        const int p0 = wbase + it * 64 + lane * 2;
        const int2 mid = *reinterpret_cast<const int2*>(mb + p0);
        float v[2][NCH];
#pragma unroll
        for (int e = 0; e < NCH; e++) {
            const float2 t = *reinterpret_cast<const float2*>(eb + (size_t)e * P + p0);
            v[0][e] = t.x; v[1][e] = t.y;
        }
        const int ids[2] = {mid.x, mid.y};
#pragma unroll
        for (int s = 0; s < 2; s++) {
            const int id = ids[s];
            const bool go = (id != 0);
            const int key = go ? id : (64 + lane);      // unique keys for id0
            const unsigned peers = __match_any_sync(FULL, key);
            const int rank = __popc(peers & below);
            const int band = rank >> 1;                 // round index
            const int rep  = rank & 1;                  // replica select
            float* a = &wacc[w][rep][(id - 1) * STR];
            for (int r = 0;; r++) {
                if (!__ballot_sync(FULL, go && band >= r)) break;
                if (go && band == r) {
#pragma unroll
                    for (int e = 0; e < NCH; e++) a[e] += v[s][e];
                    a[NCH] += 1.0f;
                }
            }
        }
    }
    __syncthreads();

    for (int i = tid; i < ACCN; i += 256) {
        float s = 0.f;
#pragma unroll
        for (int w2 = 0; w2 < 8; w2++) s += wacc[w2][0][i] + wacc[w2][1][i];
        atomicAdd(&g_acc[img][i], s);
    }
}

// Pass 2: variance hinge as a PURE REDUCTION: t * invc[id] summed per image
// (divide-by-count folded in per pixel; no per-id scatter needed).
// Block mapping reversed vs pass 1 for L2 tail reuse.
__global__ __launch_bounds__(256) void k_var(const float* __restrict__ emb,
                                             const int* __restrict__ mask) {
    __shared__ float mut[ACCN];          // row (id-1)*17: mean[0..15], slot16 = invc
    __shared__ float wred[8];
    const int tid = threadIdx.x, w = tid >> 5, lane = tid & 31;
    const int img = (NIMG - 1) - blockIdx.y;
    const int bx  = 127 - blockIdx.x;

    // FIX R6: ACCN (544) > blockDim (256) -> must loop, not a single predicated store.
    for (int i = tid; i < ACCN; i += 256) {
        const int row = i / STR, e = i % STR;
        const float rawc = g_acc[img][row * STR + NCH];
        const float cc = fmaxf(rawc, 1.f);
        mut[i] = (e == NCH) ? (1.f / cc) : (g_acc[img][row * STR + e] / cc);
    }
    __syncthreads();

    const float* eb = emb + (size_t)img * NCH * P;
    const int*   mb = mask + (size_t)img * P;
    const int wbase = bx * 2048 + w * 256;
    float vsum = 0.f;

    for (int it = 0; it < 4; ++it) {
        const int p0 = wbase + it * 64 + lane * 2;
        const int2 mid = *reinterpret_cast<const int2*>(mb + p0);
        float v[2][NCH];
#pragma unroll
        for (int e = 0; e < NCH; e++) {
            const float2 t = *reinterpret_cast<const float2*>(eb + (size_t)e * P + p0);
            v[0][e] = t.x; v[1][e] = t.y;
        }
        const int ids[2] = {mid.x, mid.y};
#pragma unroll
        for (int s = 0; s < 2; s++) {
            const int id = ids[s];
            const int row = ((id == 0) ? 1 : id) - 1;
            const float* mrow = &mut[row * STR];   // distinct ids -> distinct banks; dup -> broadcast
            float sq = 0.f;
#pragma unroll
            for (int e = 0; e < NCH; e++) {
                const float d = v[s][e] - mrow[e];
                sq = fmaf(d, d, sq);
            }
            const float pd = (sq > 0.f) ? sqrtf(sq) : 0.f;
            const float tt = fmaxf(pd - DELTA_V, 0.f);
            vsum += (id != 0) ? (tt * tt * mrow[NCH]) : 0.f;
        }
    }

#pragma unroll
    for (int o = 16; o > 0; o >>= 1) vsum += __shfl_xor_sync(FULL, vsum, o);
    if (lane == 0) wred[w] = vsum;
    __syncthreads();
    if (w == 0) {
        float s = (lane < 8) ? wred[lane] : 0.f;
#pragma unroll
        for (int o = 4; o > 0; o >>= 1) s += __shfl_xor_sync(FULL, s, o);
        if (lane == 0) atomicAdd(&g_vsum[img], s);
    }
}

__device__ __forceinline__ float wsum(float x) {
#pragma unroll
    for (int o = 16; o > 0; o >>= 1) x += __shfl_xor_sync(FULL, x, o);
    return x;
}

// Finalize: one block, warp = image. Pairwise via smem broadcast reads.
__global__ __launch_bounds__(256) void k_final(float* __restrict__ out) {
    __shared__ float smu[NIMG][32][NCH + 1];
    __shared__ float sv[NIMG], sd[NIMG], sr[NIMG], sva[NIMG];
    const int tid = threadIdx.x, w = tid >> 5, lane = tid & 31;

    const float* ga = g_acc[w];
    const float cnt = ga[lane * STR + NCH];     // lane <-> instance lane+1
    const bool pres = cnt > 0.f;
    const float cc = fmaxf(cnt, 1.f);
    float mu[NCH];
#pragma unroll
    for (int e = 0; e < NCH; e++) {
        mu[e] = ga[lane * STR + e] / cc;
        smu[w][lane][e] = mu[e];
    }
    const float var_s = g_vsum[w];
    __syncwarp();

    const unsigned pb = __ballot_sync(FULL, pres);
    const float n_inst = (float)__popc(pb);

    float sqm = 0.f;
#pragma unroll
    for (int e = 0; e < NCH; e++) sqm = fmaf(mu[e], mu[e], sqm);
    const float reg_l = pres ? ((sqm > 0.f) ? sqrtf(sqm) : 0.f) : 0.f;

    float dsum = 0.f, pcount = 0.f;
#pragma unroll 4
    for (int b = 1; b < 32; b++) {
        float dsq = 0.f;
#pragma unroll
        for (int e = 0; e < NCH; e++) {
            const float d = mu[e] - smu[w][b][e];
            dsq = fmaf(d, d, dsq);
        }
        if ((lane < b) && pres && ((pb >> b) & 1u)) {
            const float dd = (dsq > 0.f) ? sqrtf(dsq) : 0.f;
            const float tt = fmaxf(2.f * DELTA_D - dd, 0.f);
            dsum = fmaf(tt, tt, dsum);
            pcount += 1.f;
        }
    }

    const float reg_t = wsum(reg_l);
    const float dst_t = wsum(dsum);
    const float pcs   = wsum(pcount);

    if (lane == 0) {
        const float valid = (n_inst > 0.f) ? 1.f : 0.f;
        const float denom = fmaxf(n_inst, 1.f);
        sv[w]  = (var_s / denom) * valid;
        sr[w]  = (reg_t / denom) * valid;
        sd[w]  = (dst_t / fmaxf(pcs, 1.f)) * ((n_inst > 1.f) ? 1.f : 0.f) * valid;
        sva[w] = valid;
    }
    __syncthreads();

    if (tid == 0) {
        float vs = 0.f, v = 0.f, d = 0.f, r = 0.f;
        for (int i = 0; i < NIMG; i++) { vs += sva[i]; v += sv[i]; d += sd[i]; r += sr[i]; }
        vs = fmaxf(vs, 1.f);
        v /= vs; d /= vs; r /= vs;
        out[0] = v + d + GAMMA_W * r;
        out[1] = v;
        out[2] = d;
        out[3] = r;
    }

    // Re-zero scratch for the next graph replay (all reads happened above).
    float* a = &g_acc[0][0];
    for (int i = tid; i < NIMG * ACCN; i += 256) a[i] = 0.f;
    if (tid < NIMG) g_vsum[tid] = 0.f;
}

extern "C" void kernel_launch(void* const* d_in, const int* in_sizes, int n_in,
                              void* d_out, int out_size) {
    const float* emb = (const float*)d_in[0];
    const int* mask = (const int*)d_in[1];
    float* out = (float*)d_out;

    k_accum<<<dim3(128, NIMG), 256>>>(emb, mask);
    k_var<<<dim3(128, NIMG), 256>>>(emb, mask);
    k_final<<<1, 256>>>(out);
}

// round 9
// speedup vs baseline: 1.7810x; 1.0037x over previous
#include <cuda_runtime.h>
#include <math.h>

#define P 262144          // 512*512
#define NCH 16
#define NIMG 8
#define NID 32            // ids 1..32 at row id-1; id 0 excluded (never contributes)
#define STR 17            // row stride: 17 invertible mod 32 -> conflict-free scatter
#define ACCN (NID * STR)  // 544 floats per logical accumulator
#define RREP 4            // rank replicas
#define RSTR 545          // replica stride: 545 % 32 == 1 -> same-row reps hit distinct banks
#define DELTA_V 0.5f
#define DELTA_D 1.5f
#define GAMMA_W 0.001f
#define FULL 0xffffffffu

// Scratch (zero-initialized at load; k_final re-zeroes after use per replay).
__device__ float g_acc[NIMG][ACCN];   // [(id-1)*17 + e], slot 16 = count
__device__ float g_vsum[NIMG];        // per-image sum of t * invc

// Pass 1: per-segment sums + counts. grid (128, 8) x 256 thr; block = 2048 px.
// Per-warp accumulators with R=4 rank-replicas: round = rank>>2, replica = rank&3.
// Same-id lanes in one round use distinct replicas; RSTR=545 (== 1 mod 32) keeps
// those on distinct banks (R6's 544 stride aliased banks -> hidden 2-way conflict).
__global__ __launch_bounds__(256) void k_accum(const float* __restrict__ emb,
                                               const int* __restrict__ mask) {
    __shared__ float wacc[8][RREP * RSTR];   // 69.8 KB
    const int tid = threadIdx.x, w = tid >> 5, lane = tid & 31;
    const int img = blockIdx.y;

    for (int i = tid; i < 8 * RREP * RSTR; i += 256) (&wacc[0][0])[i] = 0.f;
    __syncthreads();

    const float* eb = emb + (size_t)img * NCH * P;
    const int*   mb = mask + (size_t)img * P;
    const int wbase = blockIdx.x * 2048 + w * 256;
    const unsigned below = (1u << lane) - 1u;

    for (int it = 0; it < 4; ++it) {
        const int p0 = wbase + it * 64 + lane * 2;
        const int2 mid = *reinterpret_cast<const int2*>(mb + p0);
        float v[2][NCH];
#pragma unroll
        for (int e = 0; e < NCH; e++) {
            const float2 t = *reinterpret_cast<const float2*>(eb + (size_t)e * P + p0);
            v[0][e] = t.x; v[1][e] = t.y;
        }
        const int ids[2] = {mid.x, mid.y};
#pragma unroll
        for (int s = 0; s < 2; s++) {
            const int id = ids[s];
            const bool go = (id != 0);
            const int key = go ? id : (64 + lane);        // unique keys park id0 lanes
            const unsigned peers = __match_any_sync(FULL, key);
            const int rank = __popc(peers & below);
            const int band = rank >> 2;                   // round index (<= 7)
            const int rep  = rank & 3;                    // replica select
            float* a = &wacc[w][rep * RSTR + (id - 1) * STR];
            for (int r = 0;; r++) {
                if (!__ballot_sync(FULL, go && band >= r)) break;
                if (go && band == r) {
#pragma unroll
                    for (int e = 0; e < NCH; e++) a[e] += v[s][e];
                    a[NCH] += 1.0f;
                }
            }
        }
    }
    __syncthreads();

    for (int i = tid; i < ACCN; i += 256) {
        float s = 0.f;
#pragma unroll
        for (int w2 = 0; w2 < 8; w2++) {
#pragma unroll
            for (int rp = 0; rp < RREP; rp++) s += wacc[w2][rp * RSTR + i];
        }
        atomicAdd(&g_acc[img][i], s);
    }
}

// Pass 2: variance hinge as a pure reduction: sum of t * invc[id] per image.
// float4 path: 16 back-to-back LDG.128 per 128 pixels -> high MLP, fewer instrs.
// Block mapping reversed vs pass 1 for L2 tail reuse.
__global__ __launch_bounds__(256) void k_var(const float* __restrict__ emb,
                                             const int* __restrict__ mask) {
    __shared__ float mut[ACCN];          // row (id-1)*17: mean[0..15], slot16 = invc
    __shared__ float wred[8];
    const int tid = threadIdx.x, w = tid >> 5, lane = tid & 31;
    const int img = (NIMG - 1) - blockIdx.y;
    const int bx  = 127 - blockIdx.x;

    for (int i = tid; i < ACCN; i += 256) {
        const int row = i / STR, e = i % STR;
        const float cc = fmaxf(g_acc[img][row * STR + NCH], 1.f);
        mut[i] = (e == NCH) ? (1.f / cc) : (g_acc[img][row * STR + e] / cc);
    }
    __syncthreads();

    const float* eb = emb + (size_t)img * NCH * P;
    const int*   mb = mask + (size_t)img * P;
    const int wbase = bx * 2048 + w * 256;
    float vsum = 0.f;

    for (int it = 0; it < 2; ++it) {
        const int p0 = wbase + it * 128 + lane * 4;
        const int4 mid = *reinterpret_cast<const int4*>(mb + p0);
        float v[4][NCH];
#pragma unroll
        for (int e = 0; e < NCH; e++) {
            const float4 t = *reinterpret_cast<const float4*>(eb + (size_t)e * P + p0);
            v[0][e] = t.x; v[1][e] = t.y; v[2][e] = t.z; v[3][e] = t.w;
        }
        const int ids[4] = {mid.x, mid.y, mid.z, mid.w};
#pragma unroll
        for (int s = 0; s < 4; s++) {
            const int id = ids[s];
            const int row = ((id == 0) ? 1 : id) - 1;
            const float* mrow = &mut[row * STR];   // distinct ids -> distinct banks
            float sq = 0.f;
#pragma unroll
            for (int e = 0; e < NCH; e++) {
                const float d = v[s][e] - mrow[e];
                sq = fmaf(d, d, sq);
            }
            const float pd = (sq > 0.f) ? sqrtf(sq) : 0.f;
            const float tt = fmaxf(pd - DELTA_V, 0.f);
            vsum += (id != 0) ? (tt * tt * mrow[NCH]) : 0.f;
        }
    }

#pragma unroll
    for (int o = 16; o > 0; o >>= 1) vsum += __shfl_xor_sync(FULL, vsum, o);
    if (lane == 0) wred[w] = vsum;
    __syncthreads();
    if (w == 0) {
        float s = (lane < 8) ? wred[lane] : 0.f;
#pragma unroll
        for (int o = 4; o > 0; o >>= 1) s += __shfl_xor_sync(FULL, s, o);
        if (lane == 0) atomicAdd(&g_vsum[img], s);
    }
}

__device__ __forceinline__ float wsum(float x) {
#pragma unroll
    for (int o = 16; o > 0; o >>= 1) x += __shfl_xor_sync(FULL, x, o);
    return x;
}

// Finalize: one block, warp = image. Pairwise via smem broadcast reads.
__global__ __launch_bounds__(256) void k_final(float* __restrict__ out) {
    __shared__ float smu[NIMG][32][NCH + 1];
    __shared__ float sv[NIMG], sd[NIMG], sr[NIMG], sva[NIMG];
    const int tid = threadIdx.x, w = tid >> 5, lane = tid & 31;

    const float* ga = g_acc[w];
    const float cnt = ga[lane * STR + NCH];     // lane <-> instance lane+1
    const bool pres = cnt > 0.f;
    const float cc = fmaxf(cnt, 1.f);
    float mu[NCH];
#pragma unroll
    for (int e = 0; e < NCH; e++) {
        mu[e] = ga[lane * STR + e] / cc;
        smu[w][lane][e] = mu[e];
    }
    const float var_s = g_vsum[w];
    __syncwarp();

    const unsigned pb = __ballot_sync(FULL, pres);
    const float n_inst = (float)__popc(pb);

    float sqm = 0.f;
#pragma unroll
    for (int e = 0; e < NCH; e++) sqm = fmaf(mu[e], mu[e], sqm);
    const float reg_l = pres ? ((sqm > 0.f) ? sqrtf(sqm) : 0.f) : 0.f;

    float dsum = 0.f, pcount = 0.f;
#pragma unroll 4
    for (int b = 1; b < 32; b++) {
        float dsq = 0.f;
#pragma unroll
        for (int e = 0; e < NCH; e++) {
            const float d = mu[e] - smu[w][b][e];
            dsq = fmaf(d, d, dsq);
        }
        if ((lane < b) && pres && ((pb >> b) & 1u)) {
            const float dd = (dsq > 0.f) ? sqrtf(dsq) : 0.f;
            const float tt = fmaxf(2.f * DELTA_D - dd, 0.f);
            dsum = fmaf(tt, tt, dsum);
            pcount += 1.f;
        }
    }

    const float reg_t = wsum(reg_l);
    const float dst_t = wsum(dsum);
    const float pcs   = wsum(pcount);

    if (lane == 0) {
        const float valid = (n_inst > 0.f) ? 1.f : 0.f;
        const float denom = fmaxf(n_inst, 1.f);
        sv[w]  = (var_s / denom) * valid;
        sr[w]  = (reg_t / denom) * valid;
        sd[w]  = (dst_t / fmaxf(pcs, 1.f)) * ((n_inst > 1.f) ? 1.f : 0.f) * valid;
        sva[w] = valid;
    }
    __syncthreads();

    if (tid == 0) {
        float vs = 0.f, v = 0.f, d = 0.f, r = 0.f;
        for (int i = 0; i < NIMG; i++) { vs += sva[i]; v += sv[i]; d += sd[i]; r += sr[i]; }
        vs = fmaxf(vs, 1.f);
        v /= vs; d /= vs; r /= vs;
        out[0] = v + d + GAMMA_W * r;
        out[1] = v;
        out[2] = d;
        out[3] = r;
    }

    // Re-zero scratch for the next graph replay (all reads happened above).
    float* a = &g_acc[0][0];
    for (int i = tid; i < NIMG * ACCN; i += 256) a[i] = 0.f;
    if (tid < NIMG) g_vsum[tid] = 0.f;
}

extern "C" void kernel_launch(void* const* d_in, const int* in_sizes, int n_in,
                              void* d_out, int out_size) {
    const float* emb = (const float*)d_in[0];
    const int* mask = (const int*)d_in[1];
    float* out = (float*)d_out;

    k_accum<<<dim3(128, NIMG), 256>>>(emb, mask);
    k_var<<<dim3(128, NIMG), 256>>>(emb, mask);
    k_final<<<1, 256>>>(out);
}

// round 10
// speedup vs baseline: 1.9440x; 1.0915x over previous
#include <cuda_runtime.h>
#include <math.h>

#define P 262144          // 512*512
#define NCH 16
#define NIMG 8
#define NID 32            // ids 1..32 at row id-1; id 0 excluded (never contributes)
#define STR 17            // row stride: 17 invertible mod 32 -> conflict-free scatter
#define ACCN (NID * STR)  // 544 floats per logical accumulator
#define RREP 3            // rank replicas (R=3: rounds ~1.5, smem 52.3KB -> 4 blocks/SM)
#define RSTR 545          // replica stride: 545 % 32 == 1 -> same-row reps hit distinct banks
#define DELTA_V 0.5f
#define DELTA_D 1.5f
#define GAMMA_W 0.001f
#define FULL 0xffffffffu

// Scratch (zero-initialized at load; k_final re-zeroes after use per replay).
__device__ float g_acc[NIMG][ACCN];   // [(id-1)*17 + e], slot 16 = count
__device__ float g_vsum[NIMG];        // per-image sum of t * invc

// Pass 1: per-segment sums + counts. grid (128, 8) x 256 thr; block = 2048 px.
// Per-warp accumulators, R=3 rank-replicas: round = rank/3, replica = rank%3.
// launch_bounds(...,4) caps regs at 64 so occupancy reaches 4 blocks (32 warps).
__global__ __launch_bounds__(256, 4) void k_accum(const float* __restrict__ emb,
                                                  const int* __restrict__ mask) {
    __shared__ float wacc[8][RREP * RSTR];   // 52.3 KB
    const int tid = threadIdx.x, w = tid >> 5, lane = tid & 31;
    const int img = blockIdx.y;

    for (int i = tid; i < 8 * RREP * RSTR; i += 256) (&wacc[0][0])[i] = 0.f;
    __syncthreads();

    const float* eb = emb + (size_t)img * NCH * P;
    const int*   mb = mask + (size_t)img * P;
    const int wbase = blockIdx.x * 2048 + w * 256;
    const unsigned below = (1u << lane) - 1u;

    for (int it = 0; it < 4; ++it) {
        const int p0 = wbase + it * 64 + lane * 2;
        const int2 mid = *reinterpret_cast<const int2*>(mb + p0);
        float v[2][NCH];
#pragma unroll
        for (int e = 0; e < NCH; e++) {
            const float2 t = *reinterpret_cast<const float2*>(eb + (size_t)e * P + p0);
            v[0][e] = t.x; v[1][e] = t.y;
        }
        const int ids[2] = {mid.x, mid.y};
#pragma unroll
        for (int s = 0; s < 2; s++) {
            const int id = ids[s];
            const bool go = (id != 0);
            const int key = go ? id : (64 + lane);        // unique keys park id0 lanes
            const unsigned peers = __match_any_sync(FULL, key);
            const int rank = __popc(peers & below);
            const int band = rank / RREP;                 // round index
            const int rep  = rank - band * RREP;          // replica select
            const float cntf = (float)__popc(peers);      // leader adds whole group count
            float* a = &wacc[w][rep * RSTR + (id - 1) * STR];
            for (int r = 0;; r++) {
                if (!__ballot_sync(FULL, go && band >= r)) break;
                if (go && band == r) {
#pragma unroll
                    for (int e = 0; e < NCH; e++) a[e] += v[s][e];
                    if (rank == 0) a[NCH] += cntf;        // once per id-group
                }
            }
        }
    }
    __syncthreads();

    for (int i = tid; i < ACCN; i += 256) {
        float s = 0.f;
#pragma unroll
        for (int w2 = 0; w2 < 8; w2++) {
#pragma unroll
            for (int rp = 0; rp < RREP; rp++) s += wacc[w2][rp * RSTR + i];
        }
        atomicAdd(&g_acc[img][i], s);
    }
}

// Pass 2: variance hinge as a pure reduction: sum of t * invc[id] per image.
// float2 path (float4 blew registers and killed occupancy in R9).
// Block mapping reversed vs pass 1 for L2 tail reuse.
__global__ __launch_bounds__(256, 5) void k_var(const float* __restrict__ emb,
                                                const int* __restrict__ mask) {
    __shared__ float mut[ACCN];          // row (id-1)*17: mean[0..15], slot16 = invc
    __shared__ float wred[8];
    const int tid = threadIdx.x, w = tid >> 5, lane = tid & 31;
    const int img = (NIMG - 1) - blockIdx.y;
    const int bx  = 127 - blockIdx.x;

    for (int i = tid; i < ACCN; i += 256) {
        const int row = i / STR, e = i % STR;
        const float cc = fmaxf(g_acc[img][row * STR + NCH], 1.f);
        mut[i] = (e == NCH) ? (1.f / cc) : (g_acc[img][row * STR + e] / cc);
    }
    __syncthreads();

    const float* eb = emb + (size_t)img * NCH * P;
    const int*   mb = mask + (size_t)img * P;
    const int wbase = bx * 2048 + w * 256;
    float vsum = 0.f;

    for (int it = 0; it < 4; ++it) {
        const int p0 = wbase + it * 64 + lane * 2;
        const int2 mid = *reinterpret_cast<const int2*>(mb + p0);
        float v[2][NCH];
#pragma unroll
        for (int e = 0; e < NCH; e++) {
            const float2 t = *reinterpret_cast<const float2*>(eb + (size_t)e * P + p0);
            v[0][e] = t.x; v[1][e] = t.y;
        }
        const int ids[2] = {mid.x, mid.y};
#pragma unroll
        for (int s = 0; s < 2; s++) {
            const int id = ids[s];
            const int row = ((id == 0) ? 1 : id) - 1;
            const float* mrow = &mut[row * STR];   // distinct rows -> distinct banks
            float sq = 0.f;
#pragma unroll
            for (int e = 0; e < NCH; e++) {
                const float d = v[s][e] - mrow[e];
                sq = fmaf(d, d, sq);
            }
            const float pd = (sq > 0.f) ? sqrtf(sq) : 0.f;
            const float tt = fmaxf(pd - DELTA_V, 0.f);
            vsum += (id != 0) ? (tt * tt * mrow[NCH]) : 0.f;
        }
    }

#pragma unroll
    for (int o = 16; o > 0; o >>= 1) vsum += __shfl_xor_sync(FULL, vsum, o);
    if (lane == 0) wred[w] = vsum;
    __syncthreads();
    if (w == 0) {
        float s = (lane < 8) ? wred[lane] : 0.f;
#pragma unroll
        for (int o = 4; o > 0; o >>= 1) s += __shfl_xor_sync(FULL, s, o);
        if (lane == 0) atomicAdd(&g_vsum[img], s);
    }
}

__device__ __forceinline__ float wsum(float x) {
#pragma unroll
    for (int o = 16; o > 0; o >>= 1) x += __shfl_xor_sync(FULL, x, o);
    return x;
}

// Finalize: one block, warp = image. Pairwise via smem broadcast reads.
__global__ __launch_bounds__(256) void k_final(float* __restrict__ out) {
    __shared__ float smu[NIMG][32][NCH + 1];
    __shared__ float sv[NIMG], sd[NIMG], sr[NIMG], sva[NIMG];
    const int tid = threadIdx.x, w = tid >> 5, lane = tid & 31;

    const float* ga = g_acc[w];
    const float cnt = ga[lane * STR + NCH];     // lane <-> instance lane+1
    const bool pres = cnt > 0.f;
    const float cc = fmaxf(cnt, 1.f);
    float mu[NCH];
#pragma unroll
    for (int e = 0; e < NCH; e++) {
        mu[e] = ga[lane * STR + e] / cc;
        smu[w][lane][e] = mu[e];
    }
    const float var_s = g_vsum[w];
    __syncwarp();

    const unsigned pb = __ballot_sync(FULL, pres);
    const float n_inst = (float)__popc(pb);

    float sqm = 0.f;
#pragma unroll
    for (int e = 0; e < NCH; e++) sqm = fmaf(mu[e], mu[e], sqm);
    const float reg_l = pres ? ((sqm > 0.f) ? sqrtf(sqm) : 0.f) : 0.f;

    float dsum = 0.f, pcount = 0.f;
#pragma unroll 4
    for (int b = 1; b < 32; b++) {
        float dsq = 0.f;
#pragma unroll
        for (int e = 0; e < NCH; e++) {
            const float d = mu[e] - smu[w][b][e];
            dsq = fmaf(d, d, dsq);
        }
        if ((lane < b) && pres && ((pb >> b) & 1u)) {
            const float dd = (dsq > 0.f) ? sqrtf(dsq) : 0.f;
            const float tt = fmaxf(2.f * DELTA_D - dd, 0.f);
            dsum = fmaf(tt, tt, dsum);
            pcount += 1.f;
        }
    }

    const float reg_t = wsum(reg_l);
    const float dst_t = wsum(dsum);
    const float pcs   = wsum(pcount);

    if (lane == 0) {
        const float valid = (n_inst > 0.f) ? 1.f : 0.f;
        const float denom = fmaxf(n_inst, 1.f);
        sv[w]  = (var_s / denom) * valid;
        sr[w]  = (reg_t / denom) * valid;
        sd[w]  = (dst_t / fmaxf(pcs, 1.f)) * ((n_inst > 1.f) ? 1.f : 0.f) * valid;
        sva[w] = valid;
    }
    __syncthreads();

    if (tid == 0) {
        float vs = 0.f, v = 0.f, d = 0.f, r = 0.f;
        for (int i = 0; i < NIMG; i++) { vs += sva[i]; v += sv[i]; d += sd[i]; r += sr[i]; }
        vs = fmaxf(vs, 1.f);
        v /= vs; d /= vs; r /= vs;
        out[0] = v + d + GAMMA_W * r;
        out[1] = v;
        out[2] = d;
        out[3] = r;
    }

    // Re-zero scratch for the next graph replay (all reads happened above).
    float* a = &g_acc[0][0];
    for (int i = tid; i < NIMG * ACCN; i += 256) a[i] = 0.f;
    if (tid < NIMG) g_vsum[tid] = 0.f;
}

extern "C" void kernel_launch(void* const* d_in, const int* in_sizes, int n_in,
                              void* d_out, int out_size) {
    const float* emb = (const float*)d_in[0];
    const int* mask = (const int*)d_in[1];
    float* out = (float*)d_out;

    k_accum<<<dim3(128, NIMG), 256>>>(emb, mask);
    k_var<<<dim3(128, NIMG), 256>>>(emb, mask);
    k_final<<<1, 256>>>(out);
}